// round 11
// baseline (speedup 1.0000x reference)
#include <cuda_runtime.h>
#include <math.h>

// ---------------- problem dims ----------------
#define NBATCH 64
#define SEQ    256
#define EDIM   352
#define HID    384
#define GATE   1536   // 4*HID
#define DD2    768    // 2*HID
#define ADIM   512
#define NHEAD  4
#define HDIM   128
#define NLAB   31

// ---------------- scratch (device globals; no cudaMalloc allowed) ----------------
__device__ float g_emb   [NBATCH*SEQ*EDIM];
__device__ float g_xwf   [NBATCH*SEQ*GATE];
__device__ float g_xwb   [NBATCH*SEQ*GATE];
__device__ float g_h1    [NBATCH*SEQ*DD2];
__device__ float g_h2    [NBATCH*SEQ*DD2];
__device__ float g_q     [NBATCH*SEQ*ADIM];
__device__ float g_k     [NBATCH*SEQ*ADIM];
__device__ float g_v     [NBATCH*SEQ*ADIM];
__device__ float g_s     [NBATCH*NHEAD*SEQ*SEQ];
__device__ float g_z     [NBATCH*SEQ*ADIM];
__device__ float g_ao    [NBATCH*SEQ*ADIM];
__device__ float g_logits[NBATCH*SEQ*NLAB];
__device__ float g_ll    [NBATCH];
__device__ int   g_lens  [NBATCH];
__device__ int   g_pred  [NBATCH*SEQ];

// XLA LogisticExpander form: logistic(x) = 0.5 + 0.5 * tanh(0.5 * x)
__device__ __forceinline__ float xla_sigmoid(float x) {
    return __fadd_rn(0.5f, __fmul_rn(0.5f, tanhf(__fmul_rn(0.5f, x))));
}

// ---------------- embedding concat ----------------
__global__ void embed_k(const int* __restrict__ chars, const int* __restrict__ bounds,
                        const int* __restrict__ flags, const int* __restrict__ radicals,
                        const int* __restrict__ pinyins,
                        const float* __restrict__ ec, const float* __restrict__ eb,
                        const float* __restrict__ ef, const float* __restrict__ er,
                        const float* __restrict__ ep, float* __restrict__ emb)
{
    int bt = blockIdx.x;
    int f  = threadIdx.x; // 0..351
    float v;
    if      (f < 128) v = ec[(long)chars[bt]   *128 + f];
    else if (f < 160) v = eb[(long)bounds[bt]  *32  + (f-128)];
    else if (f < 224) v = ef[(long)flags[bt]   *64  + (f-160)];
    else if (f < 288) v = er[(long)radicals[bt]*64  + (f-224)];
    else              v = ep[(long)pinyins[bt] *64  + (f-288)];
    emb[(long)bt*EDIM + f] = v;
}

__global__ void lens_k(const int* __restrict__ chars, int* __restrict__ lens)
{
    __shared__ int cnt;
    if (threadIdx.x == 0) cnt = 0;
    __syncthreads();
    int c = chars[blockIdx.x*SEQ + threadIdx.x];
    int sg = (c > 0) - (c < 0);
    atomicAdd(&cnt, sg);
    __syncthreads();
    if (threadIdx.x == 0) lens[blockIdx.x] = cnt;
}

// ---------------- generic tiled GEMM (exact fp32, fma accumulate) ----------------
template<bool TRANSB, bool BIAS>
__global__ __launch_bounds__(256)
void gemm_k(const float* __restrict__ A0, const float* __restrict__ B0,
            const float* __restrict__ bias, float* __restrict__ C0,
            int M, int N, int K, int lda, int ldb, int ldc,
            long sAo, long sAi, long sBo, long sBi, long sCo, long sCi, int nInner)
{
    int z  = blockIdx.z;
    int zo = z / nInner, zi = z - zo*nInner;
    const float* A  = A0 + zo*sAo + zi*sAi;
    const float* Bp = B0 + zo*sBo + zi*sBi;
    float*       C  = C0 + zo*sCo + zi*sCi;

    int m0 = blockIdx.y*128, n0 = blockIdx.x*128;
    __shared__ float As[8][128];
    __shared__ float Bs[8][128];

    int tid = threadIdx.x;
    int ty = tid >> 4, tx = tid & 15;

    float acc[8][8];
#pragma unroll
    for (int i = 0; i < 8; i++)
#pragma unroll
        for (int j = 0; j < 8; j++) acc[i][j] = 0.f;

    const int ar = tid >> 1, ak = (tid & 1) << 2;
    const bool bvec_ok = ((ldb & 3) == 0);

    for (int k0 = 0; k0 < K; k0 += 8) {
        float4 av = make_float4(0.f,0.f,0.f,0.f);
        if (m0 + ar < M)
            av = *(const float4*)(A + (long)(m0+ar)*lda + k0 + ak);
        As[ak+0][ar]=av.x; As[ak+1][ar]=av.y; As[ak+2][ar]=av.z; As[ak+3][ar]=av.w;

        if (TRANSB) {
            int br = tid >> 1, bk = (tid & 1) << 2;
            float4 bv = make_float4(0.f,0.f,0.f,0.f);
            if (n0 + br < N)
                bv = *(const float4*)(Bp + (long)(n0+br)*ldb + k0 + bk);
            Bs[bk+0][br]=bv.x; Bs[bk+1][br]=bv.y; Bs[bk+2][br]=bv.z; Bs[bk+3][br]=bv.w;
        } else {
            int bk = tid >> 5, bn = (tid & 31) << 2;
            const float* pb = Bp + (long)(k0+bk)*ldb + n0 + bn;
            if (bvec_ok && (n0 + bn + 4 <= N)) {
                float4 bv = *(const float4*)pb;
                Bs[bk][bn+0]=bv.x; Bs[bk][bn+1]=bv.y; Bs[bk][bn+2]=bv.z; Bs[bk][bn+3]=bv.w;
            } else {
#pragma unroll
                for (int i = 0; i < 4; i++)
                    Bs[bk][bn+i] = (n0 + bn + i < N) ? pb[i] : 0.f;
            }
        }
        __syncthreads();

#pragma unroll
        for (int kk = 0; kk < 8; kk++) {
            float a[8], b[8];
            *(float4*)(a)   = *(const float4*)&As[kk][ty<<3];
            *(float4*)(a+4) = *(const float4*)&As[kk][(ty<<3)+4];
            *(float4*)(b)   = *(const float4*)&Bs[kk][tx<<3];
            *(float4*)(b+4) = *(const float4*)&Bs[kk][(tx<<3)+4];
#pragma unroll
            for (int i = 0; i < 8; i++)
#pragma unroll
                for (int j = 0; j < 8; j++)
                    acc[i][j] = fmaf(a[i], b[j], acc[i][j]);
        }
        __syncthreads();
    }

#pragma unroll
    for (int i = 0; i < 8; i++) {
        int row = m0 + (ty<<3) + i;
        if (row >= M) continue;
#pragma unroll
        for (int j = 0; j < 8; j++) {
            int col = n0 + (tx<<3) + j;
            if (col < N) {
                float v = acc[i][j];
                if (BIAS) v = __fadd_rn(v, bias[col]);
                C[(long)row*ldc + col] = v;
            }
        }
    }
}

// ---------------- LSTM recurrence (exact fp32) ----------------
__global__ __launch_bounds__(384)
void lstm_k(const float* __restrict__ xwF, const float* __restrict__ xwB,
            const float* __restrict__ WhF, const float* __restrict__ WhB,
            float* __restrict__ out)
{
    const int dir = blockIdx.y;
    const int b0  = blockIdx.x * 2;
    const float* xw = dir ? xwB : xwF;
    const float* Wh = dir ? WhB : WhF;

    __shared__ float2 hs[HID];
    __shared__ float  zs[2][GATE];

    const int u = threadIdx.x;
    float c0 = 0.f, c1 = 0.f;
    hs[u] = make_float2(0.f, 0.f);
    __syncthreads();

    const float* w = Wh + 4*u;

    for (int t = 0; t < SEQ; t++) {
        const int tin = dir ? (SEQ-1-t) : t;
        float4 a0 = *(const float4*)&xw[((long)(b0+0)*SEQ + tin)*GATE + 4*u];
        float4 a1 = *(const float4*)&xw[((long)(b0+1)*SEQ + tin)*GATE + 4*u];

#pragma unroll 8
        for (int k = 0; k < HID; k++) {
            float4 wv = *(const float4*)&w[(long)k*GATE];
            float2 h = hs[k];
            a0.x = fmaf(h.x, wv.x, a0.x); a0.y = fmaf(h.x, wv.y, a0.y);
            a0.z = fmaf(h.x, wv.z, a0.z); a0.w = fmaf(h.x, wv.w, a0.w);
            a1.x = fmaf(h.y, wv.x, a1.x); a1.y = fmaf(h.y, wv.y, a1.y);
            a1.z = fmaf(h.y, wv.z, a1.z); a1.w = fmaf(h.y, wv.w, a1.w);
        }
        *(float4*)&zs[0][4*u] = a0;
        *(float4*)&zs[1][4*u] = a1;
        __syncthreads();

        float zi0 = zs[0][u], zf0 = zs[0][u+HID], zg0 = zs[0][u+2*HID], zo0 = zs[0][u+3*HID];
        float zi1 = zs[1][u], zf1 = zs[1][u+HID], zg1 = zs[1][u+2*HID], zo1 = zs[1][u+3*HID];
        float i0 = xla_sigmoid(zi0), f0 = xla_sigmoid(zf0), o0 = xla_sigmoid(zo0);
        float i1 = xla_sigmoid(zi1), f1 = xla_sigmoid(zf1), o1 = xla_sigmoid(zo1);
        c0 = __fadd_rn(__fmul_rn(f0, c0), __fmul_rn(i0, tanhf(zg0)));
        c1 = __fadd_rn(__fmul_rn(f1, c1), __fmul_rn(i1, tanhf(zg1)));
        float h0 = __fmul_rn(o0, tanhf(c0));
        float h1 = __fmul_rn(o1, tanhf(c1));
        hs[u] = make_float2(h0, h1);
        out[((long)(b0+0)*SEQ + t)*DD2 + dir*HID + u] = h0;
        out[((long)(b0+1)*SEQ + t)*DD2 + dir*HID + u] = h1;
        __syncthreads();
    }
}

// ---------------- masked, scaled softmax over key dim ----------------
__global__ void softmax_k(float* __restrict__ s, const int* __restrict__ lens)
{
    long row = blockIdx.x;
    int  b   = blockIdx.x >> 10;
    float* p = s + row*SEQ;
    int len  = lens[b];
    int j    = threadIdx.x;

    const float rs = sqrtf(512.0f);
    float raw = (j < len) ? p[j] : -4294967296.0f;
    float v = __fdiv_rn(raw, rs);

    __shared__ float red[256];
    red[j] = v; __syncthreads();
    for (int o = 128; o > 0; o >>= 1) { if (j < o) red[j] = fmaxf(red[j], red[j+o]); __syncthreads(); }
    float m = red[0]; __syncthreads();
    float e = expf(__fadd_rn(v, -m));
    red[j] = e; __syncthreads();
    for (int o = 128; o > 0; o >>= 1) { if (j < o) red[j] += red[j+o]; __syncthreads(); }
    p[j] = __fdiv_rn(e, red[0]);
}

// ---------------- CRF log-likelihood (per batch) ----------------
__global__ void crf_ll_k(const float* __restrict__ logits, const int* __restrict__ labels,
                         const int* __restrict__ lens, const float* __restrict__ trans,
                         float* __restrict__ ll)
{
    int b = blockIdx.x, j = threadIdx.x;
    __shared__ float tr[NLAB*NLAB];
    __shared__ float alpha[NLAB];
    for (int i = j; i < NLAB*NLAB; i += 32) tr[i] = trans[i];

    int len = lens[b];
    const float* lg = logits + (long)b*SEQ*NLAB;
    const int*   tg = labels + b*SEQ;

    float un = 0.f, bi = 0.f;
    for (int t = j; t < SEQ; t += 32) {
        if (t < len)                 un += lg[t*NLAB + tg[t]];
        if (t < SEQ-1 && t < len-1)  bi += trans[tg[t]*NLAB + tg[t+1]];
    }
    for (int o = 16; o > 0; o >>= 1) {
        un += __shfl_down_sync(0xffffffffu, un, o);
        bi += __shfl_down_sync(0xffffffffu, bi, o);
    }
    __syncwarp();
    if (j < NLAB) alpha[j] = lg[j];
    __syncwarp();

    int tend = len - 1;
    for (int t = 1; t <= tend; t++) {
        float na = 0.f;
        if (j < NLAB) {
            float m = -3.4e38f;
            for (int i = 0; i < NLAB; i++) m = fmaxf(m, alpha[i] + tr[i*NLAB + j]);
            float s = 0.f;
            for (int i = 0; i < NLAB; i++) s += expf(alpha[i] + tr[i*NLAB + j] - m);
            na = lg[t*NLAB + j] + m + logf(s);
        }
        __syncwarp();
        if (j < NLAB) alpha[j] = na;
        __syncwarp();
    }
    if (j == 0) {
        float m = -3.4e38f;
        for (int i = 0; i < NLAB; i++) m = fmaxf(m, alpha[i]);
        float s = 0.f;
        for (int i = 0; i < NLAB; i++) s += expf(alpha[i] - m);
        float lognorm = m + logf(s);
        ll[b] = (un + bi) - lognorm;
    }
}

// ---------------- Viterbi decode (per batch, shuffle-based, shared bp) ----------------
__global__ __launch_bounds__(32)
void viterbi_k(const float* __restrict__ logits, const float* __restrict__ trans,
               int* __restrict__ pred)
{
    const int b = blockIdx.x;
    const int j = threadIdx.x;
    const bool act = (j < NLAB);
    const int jj = act ? j : 0;

    __shared__ float tr[NLAB*NLAB];
    __shared__ int   bp[SEQ][NLAB];

    for (int i = j; i < NLAB*NLAB; i += 32) tr[i] = trans[i];
    __syncwarp();

    const float* lg = logits + (long)b*SEQ*NLAB;
    float vj = lg[jj];

    for (int t = 1; t < SEQ; t++) {
        float best = -3.4e38f;
        int   bi   = 0;
#pragma unroll
        for (int i = 0; i < NLAB; i++) {
            float vi = __shfl_sync(0xffffffffu, vj, i);
            float sc = __fadd_rn(vi, tr[i*NLAB + jj]);
            if (sc > best) { best = sc; bi = i; }   // first-max == jnp.argmax
        }
        vj = __fadd_rn(lg[t*NLAB + jj], best);
        if (act) bp[t][j] = bi;
    }

    float best = -3.4e38f;
    int   bt   = 0;
#pragma unroll
    for (int i = 0; i < NLAB; i++) {
        float vi = __shfl_sync(0xffffffffu, vj, i);
        if (vi > best) { best = vi; bt = i; }
    }
    __syncwarp();

    if (j == 0) {
        int cur = bt;
        pred[b*SEQ + SEQ-1] = cur;
        for (int t = SEQ-1; t >= 1; t--) {
            cur = bp[t][cur];
            pred[b*SEQ + t-1] = cur;
        }
    }
}

// ---------------- finalize: packed layout [loss | pred(B,T) | lens(B)] ----------------
__global__ void finalize_k(const float* __restrict__ ll, const int* __restrict__ pred,
                           const int* __restrict__ lens, float* __restrict__ out, int out_size)
{
    int idx = blockIdx.x*blockDim.x + threadIdx.x;
    if (idx == 0) {
        float s = 0.f;
        for (int b = 0; b < NBATCH; b++) s += ll[b];
        out[0] = -s / (float)NBATCH;
    }
    if (idx < NBATCH*SEQ && 1 + idx < out_size) out[1 + idx] = (float)pred[idx];
    if (idx < NBATCH && 1 + NBATCH*SEQ + idx < out_size) out[1 + NBATCH*SEQ + idx] = (float)lens[idx];
}

// ---------------- host glue ----------------
static void run_gemm(bool transb, const float* A, const float* Bm, const float* bias, float* C,
                     int M, int N, int K, int lda, int ldb, int ldc,
                     long sAo, long sAi, long sBo, long sBi, long sCo, long sCi,
                     int nInner, int batch)
{
    dim3 grid((N+127)/128, (M+127)/128, batch);
    if (transb) {
        if (bias) gemm_k<true ,true ><<<grid,256>>>(A,Bm,bias,C,M,N,K,lda,ldb,ldc,sAo,sAi,sBo,sBi,sCo,sCi,nInner);
        else      gemm_k<true ,false><<<grid,256>>>(A,Bm,bias,C,M,N,K,lda,ldb,ldc,sAo,sAi,sBo,sBi,sCo,sCi,nInner);
    } else {
        if (bias) gemm_k<false,true ><<<grid,256>>>(A,Bm,bias,C,M,N,K,lda,ldb,ldc,sAo,sAi,sBo,sBi,sCo,sCi,nInner);
        else      gemm_k<false,false><<<grid,256>>>(A,Bm,bias,C,M,N,K,lda,ldb,ldc,sAo,sAi,sBo,sBi,sCo,sCi,nInner);
    }
}

extern "C" void kernel_launch(void* const* d_in, const int* in_sizes, int n_in,
                              void* d_out, int out_size)
{
    const int* chars    = (const int*)d_in[0];
    const int* bounds   = (const int*)d_in[1];
    const int* flags    = (const int*)d_in[2];
    const int* radicals = (const int*)d_in[3];
    const int* pinyins  = (const int*)d_in[4];
    const int* labels   = (const int*)d_in[5];
    const float* e_char = (const float*)d_in[6];
    const float* e_bnd  = (const float*)d_in[7];
    const float* e_flag = (const float*)d_in[8];
    const float* e_rad  = (const float*)d_in[9];
    const float* e_pin  = (const float*)d_in[10];
    const float* Wx1f = (const float*)d_in[11], *Wh1f = (const float*)d_in[12], *b1f = (const float*)d_in[13];
    const float* Wx1b = (const float*)d_in[14], *Wh1b = (const float*)d_in[15], *b1b = (const float*)d_in[16];
    const float* Wx2f = (const float*)d_in[17], *Wh2f = (const float*)d_in[18], *b2f = (const float*)d_in[19];
    const float* Wx2b = (const float*)d_in[20], *Wh2b = (const float*)d_in[21], *b2b = (const float*)d_in[22];
    const float* Wq = (const float*)d_in[23], *Wk = (const float*)d_in[24], *Wv = (const float*)d_in[25];
    const float* Wo = (const float*)d_in[26], *bo = (const float*)d_in[27];
    const float* Wcrf = (const float*)d_in[28], *trans = (const float*)d_in[29];

    float *emb, *xwf, *xwb, *h1, *h2, *q, *k, *v, *s, *z, *ao, *logits, *ll;
    int *lens, *pred;
    cudaGetSymbolAddress((void**)&emb,    g_emb);
    cudaGetSymbolAddress((void**)&xwf,    g_xwf);
    cudaGetSymbolAddress((void**)&xwb,    g_xwb);
    cudaGetSymbolAddress((void**)&h1,     g_h1);
    cudaGetSymbolAddress((void**)&h2,     g_h2);
    cudaGetSymbolAddress((void**)&q,      g_q);
    cudaGetSymbolAddress((void**)&k,      g_k);
    cudaGetSymbolAddress((void**)&v,      g_v);
    cudaGetSymbolAddress((void**)&s,      g_s);
    cudaGetSymbolAddress((void**)&z,      g_z);
    cudaGetSymbolAddress((void**)&ao,     g_ao);
    cudaGetSymbolAddress((void**)&logits, g_logits);
    cudaGetSymbolAddress((void**)&ll,     g_ll);
    cudaGetSymbolAddress((void**)&lens,   g_lens);
    cudaGetSymbolAddress((void**)&pred,   g_pred);

    const int M = NBATCH*SEQ; // 16384

    embed_k<<<M, EDIM>>>(chars, bounds, flags, radicals, pinyins,
                         e_char, e_bnd, e_flag, e_rad, e_pin, emb);
    lens_k<<<NBATCH, SEQ>>>(chars, lens);

    run_gemm(false, emb, Wx1f, b1f, xwf, M, GATE, EDIM, EDIM, GATE, GATE, 0,0,0,0,0,0, 1, 1);
    run_gemm(false, emb, Wx1b, b1b, xwb, M, GATE, EDIM, EDIM, GATE, GATE, 0,0,0,0,0,0, 1, 1);
    lstm_k<<<dim3(NBATCH/2, 2), HID>>>(xwf, xwb, Wh1f, Wh1b, h1);

    run_gemm(false, h1, Wx2f, b2f, xwf, M, GATE, DD2, DD2, GATE, GATE, 0,0,0,0,0,0, 1, 1);
    run_gemm(false, h1, Wx2b, b2b, xwb, M, GATE, DD2, DD2, GATE, GATE, 0,0,0,0,0,0, 1, 1);
    lstm_k<<<dim3(NBATCH/2, 2), HID>>>(xwf, xwb, Wh2f, Wh2b, h2);

    run_gemm(false, h2, Wq, nullptr, q, M, ADIM, DD2, DD2, ADIM, ADIM, 0,0,0,0,0,0, 1, 1);
    run_gemm(false, h2, Wk, nullptr, k, M, ADIM, DD2, DD2, ADIM, ADIM, 0,0,0,0,0,0, 1, 1);
    run_gemm(false, h2, Wv, nullptr, v, M, ADIM, DD2, DD2, ADIM, ADIM, 0,0,0,0,0,0, 1, 1);

    // scores S[b,h] = Q[b,:,h*128:...] @ K^T  (batched, TRANSB)
    run_gemm(true, q, k, nullptr, s, SEQ, SEQ, HDIM, ADIM, ADIM, SEQ,
             (long)SEQ*ADIM, HDIM, (long)SEQ*ADIM, HDIM,
             (long)NHEAD*SEQ*SEQ, (long)SEQ*SEQ, NHEAD, NBATCH*NHEAD);
    softmax_k<<<NBATCH*NHEAD*SEQ, SEQ>>>(s, lens);

    // Z[b,h] = P @ V[b,:,h*128:...]  — stored contiguously as (b, h, q, d):
    // reading g_z as (B, T, 512) row-major reproduces the reference's
    // Z.reshape(B, T, H*d) (reinterpret of (B,H,T,d) without transpose back).
    run_gemm(false, s, v, nullptr, z, SEQ, HDIM, SEQ, SEQ, ADIM, HDIM,
             (long)NHEAD*SEQ*SEQ, (long)SEQ*SEQ, (long)SEQ*ADIM, HDIM,
             (long)SEQ*ADIM, (long)SEQ*HDIM, NHEAD, NBATCH*NHEAD);

    run_gemm(false, z, Wo, bo, ao, M, ADIM, ADIM, ADIM, ADIM, ADIM, 0,0,0,0,0,0, 1, 1);
    run_gemm(false, ao, Wcrf, nullptr, logits, M, NLAB, ADIM, ADIM, NLAB, NLAB, 0,0,0,0,0,0, 1, 1);

    crf_ll_k<<<NBATCH, 32>>>(logits, labels, lens, trans, ll);
    viterbi_k<<<NBATCH, 32>>>(logits, trans, pred);
    finalize_k<<<(NBATCH*SEQ + 255)/256, 256>>>(ll, pred, lens, (float*)d_out, out_size);
}

// round 12
// speedup vs baseline: 1.0050x; 1.0050x over previous
#include <cuda_runtime.h>
#include <math.h>

// ---------------- problem dims ----------------
#define NBATCH 64
#define SEQ    256
#define EDIM   352
#define HID    384
#define GATE   1536   // 4*HID
#define DD2    768    // 2*HID
#define ADIM   512
#define NHEAD  4
#define HDIM   128
#define NLAB   31

// ---------------- scratch (device globals; no cudaMalloc allowed) ----------------
__device__ float g_emb   [NBATCH*SEQ*EDIM];
__device__ float g_xwf   [NBATCH*SEQ*GATE];
__device__ float g_xwb   [NBATCH*SEQ*GATE];
__device__ float g_h1    [NBATCH*SEQ*DD2];
__device__ float g_h2    [NBATCH*SEQ*DD2];
__device__ float g_q     [NBATCH*SEQ*ADIM];
__device__ float g_k     [NBATCH*SEQ*ADIM];
__device__ float g_v     [NBATCH*SEQ*ADIM];
__device__ float g_s     [NBATCH*NHEAD*SEQ*SEQ];
__device__ float g_z     [NBATCH*SEQ*ADIM];
__device__ float g_ao    [NBATCH*SEQ*ADIM];
__device__ float g_logits[NBATCH*SEQ*NLAB];
__device__ float g_ll    [NBATCH];
__device__ int   g_lens  [NBATCH];
__device__ int   g_pred  [NBATCH*SEQ];

// XLA LogisticExpander form: logistic(x) = 0.5 + 0.5 * tanh(0.5 * x)
__device__ __forceinline__ float xla_sigmoid(float x) {
    return __fadd_rn(0.5f, __fmul_rn(0.5f, tanhf(__fmul_rn(0.5f, x))));
}

// ---------------- embedding concat ----------------
__global__ void embed_k(const int* __restrict__ chars, const int* __restrict__ bounds,
                        const int* __restrict__ flags, const int* __restrict__ radicals,
                        const int* __restrict__ pinyins,
                        const float* __restrict__ ec, const float* __restrict__ eb,
                        const float* __restrict__ ef, const float* __restrict__ er,
                        const float* __restrict__ ep, float* __restrict__ emb)
{
    int bt = blockIdx.x;
    int f  = threadIdx.x; // 0..351
    float v;
    if      (f < 128) v = ec[(long)chars[bt]   *128 + f];
    else if (f < 160) v = eb[(long)bounds[bt]  *32  + (f-128)];
    else if (f < 224) v = ef[(long)flags[bt]   *64  + (f-160)];
    else if (f < 288) v = er[(long)radicals[bt]*64  + (f-224)];
    else              v = ep[(long)pinyins[bt] *64  + (f-288)];
    emb[(long)bt*EDIM + f] = v;
}

__global__ void lens_k(const int* __restrict__ chars, int* __restrict__ lens)
{
    __shared__ int cnt;
    if (threadIdx.x == 0) cnt = 0;
    __syncthreads();
    int c = chars[blockIdx.x*SEQ + threadIdx.x];
    int sg = (c > 0) - (c < 0);
    atomicAdd(&cnt, sg);
    __syncthreads();
    if (threadIdx.x == 0) lens[blockIdx.x] = cnt;
}

// ---------------- generic tiled GEMM (exact fp32, fma accumulate) ----------------
template<bool TRANSB, bool BIAS>
__global__ __launch_bounds__(256)
void gemm_k(const float* __restrict__ A0, const float* __restrict__ B0,
            const float* __restrict__ bias, float* __restrict__ C0,
            int M, int N, int K, int lda, int ldb, int ldc,
            long sAo, long sAi, long sBo, long sBi, long sCo, long sCi, int nInner)
{
    int z  = blockIdx.z;
    int zo = z / nInner, zi = z - zo*nInner;
    const float* A  = A0 + zo*sAo + zi*sAi;
    const float* Bp = B0 + zo*sBo + zi*sBi;
    float*       C  = C0 + zo*sCo + zi*sCi;

    int m0 = blockIdx.y*128, n0 = blockIdx.x*128;
    __shared__ float As[8][128];
    __shared__ float Bs[8][128];

    int tid = threadIdx.x;
    int ty = tid >> 4, tx = tid & 15;

    float acc[8][8];
#pragma unroll
    for (int i = 0; i < 8; i++)
#pragma unroll
        for (int j = 0; j < 8; j++) acc[i][j] = 0.f;

    const int ar = tid >> 1, ak = (tid & 1) << 2;
    const bool bvec_ok = ((ldb & 3) == 0);

    for (int k0 = 0; k0 < K; k0 += 8) {
        float4 av = make_float4(0.f,0.f,0.f,0.f);
        if (m0 + ar < M)
            av = *(const float4*)(A + (long)(m0+ar)*lda + k0 + ak);
        As[ak+0][ar]=av.x; As[ak+1][ar]=av.y; As[ak+2][ar]=av.z; As[ak+3][ar]=av.w;

        if (TRANSB) {
            int br = tid >> 1, bk = (tid & 1) << 2;
            float4 bv = make_float4(0.f,0.f,0.f,0.f);
            if (n0 + br < N)
                bv = *(const float4*)(Bp + (long)(n0+br)*ldb + k0 + bk);
            Bs[bk+0][br]=bv.x; Bs[bk+1][br]=bv.y; Bs[bk+2][br]=bv.z; Bs[bk+3][br]=bv.w;
        } else {
            int bk = tid >> 5, bn = (tid & 31) << 2;
            const float* pb = Bp + (long)(k0+bk)*ldb + n0 + bn;
            if (bvec_ok && (n0 + bn + 4 <= N)) {
                float4 bv = *(const float4*)pb;
                Bs[bk][bn+0]=bv.x; Bs[bk][bn+1]=bv.y; Bs[bk][bn+2]=bv.z; Bs[bk][bn+3]=bv.w;
            } else {
#pragma unroll
                for (int i = 0; i < 4; i++)
                    Bs[bk][bn+i] = (n0 + bn + i < N) ? pb[i] : 0.f;
            }
        }
        __syncthreads();

#pragma unroll
        for (int kk = 0; kk < 8; kk++) {
            float a[8], b[8];
            *(float4*)(a)   = *(const float4*)&As[kk][ty<<3];
            *(float4*)(a+4) = *(const float4*)&As[kk][(ty<<3)+4];
            *(float4*)(b)   = *(const float4*)&Bs[kk][tx<<3];
            *(float4*)(b+4) = *(const float4*)&Bs[kk][(tx<<3)+4];
#pragma unroll
            for (int i = 0; i < 8; i++)
#pragma unroll
                for (int j = 0; j < 8; j++)
                    acc[i][j] = fmaf(a[i], b[j], acc[i][j]);
        }
        __syncthreads();
    }

#pragma unroll
    for (int i = 0; i < 8; i++) {
        int row = m0 + (ty<<3) + i;
        if (row >= M) continue;
#pragma unroll
        for (int j = 0; j < 8; j++) {
            int col = n0 + (tx<<3) + j;
            if (col < N) {
                float v = acc[i][j];
                if (BIAS) v = __fadd_rn(v, bias[col]);
                C[(long)row*ldc + col] = v;
            }
        }
    }
}

// ---------------- LSTM recurrence (exact fp32) ----------------
__global__ __launch_bounds__(384)
void lstm_k(const float* __restrict__ xwF, const float* __restrict__ xwB,
            const float* __restrict__ WhF, const float* __restrict__ WhB,
            float* __restrict__ out)
{
    const int dir = blockIdx.y;
    const int b0  = blockIdx.x * 2;
    const float* xw = dir ? xwB : xwF;
    const float* Wh = dir ? WhB : WhF;

    __shared__ float2 hs[HID];
    __shared__ float  zs[2][GATE];

    const int u = threadIdx.x;
    float c0 = 0.f, c1 = 0.f;
    hs[u] = make_float2(0.f, 0.f);
    __syncthreads();

    const float* w = Wh + 4*u;

    for (int t = 0; t < SEQ; t++) {
        const int tin = dir ? (SEQ-1-t) : t;
        float4 a0 = *(const float4*)&xw[((long)(b0+0)*SEQ + tin)*GATE + 4*u];
        float4 a1 = *(const float4*)&xw[((long)(b0+1)*SEQ + tin)*GATE + 4*u];

#pragma unroll 8
        for (int k = 0; k < HID; k++) {
            float4 wv = *(const float4*)&w[(long)k*GATE];
            float2 h = hs[k];
            a0.x = fmaf(h.x, wv.x, a0.x); a0.y = fmaf(h.x, wv.y, a0.y);
            a0.z = fmaf(h.x, wv.z, a0.z); a0.w = fmaf(h.x, wv.w, a0.w);
            a1.x = fmaf(h.y, wv.x, a1.x); a1.y = fmaf(h.y, wv.y, a1.y);
            a1.z = fmaf(h.y, wv.z, a1.z); a1.w = fmaf(h.y, wv.w, a1.w);
        }
        *(float4*)&zs[0][4*u] = a0;
        *(float4*)&zs[1][4*u] = a1;
        __syncthreads();

        float zi0 = zs[0][u], zf0 = zs[0][u+HID], zg0 = zs[0][u+2*HID], zo0 = zs[0][u+3*HID];
        float zi1 = zs[1][u], zf1 = zs[1][u+HID], zg1 = zs[1][u+2*HID], zo1 = zs[1][u+3*HID];
        float i0 = xla_sigmoid(zi0), f0 = xla_sigmoid(zf0), o0 = xla_sigmoid(zo0);
        float i1 = xla_sigmoid(zi1), f1 = xla_sigmoid(zf1), o1 = xla_sigmoid(zo1);
        c0 = __fadd_rn(__fmul_rn(f0, c0), __fmul_rn(i0, tanhf(zg0)));
        c1 = __fadd_rn(__fmul_rn(f1, c1), __fmul_rn(i1, tanhf(zg1)));
        float h0 = __fmul_rn(o0, tanhf(c0));
        float h1 = __fmul_rn(o1, tanhf(c1));
        hs[u] = make_float2(h0, h1);
        out[((long)(b0+0)*SEQ + t)*DD2 + dir*HID + u] = h0;
        out[((long)(b0+1)*SEQ + t)*DD2 + dir*HID + u] = h1;
        __syncthreads();
    }
}

// ---------------- masked, scaled softmax over key dim ----------------
__global__ void softmax_k(float* __restrict__ s, const int* __restrict__ lens)
{
    long row = blockIdx.x;
    int  b   = blockIdx.x >> 10;
    float* p = s + row*SEQ;
    int len  = lens[b];
    int j    = threadIdx.x;

    const float rs = sqrtf(512.0f);
    float raw = (j < len) ? p[j] : -4294967296.0f;
    float v = __fdiv_rn(raw, rs);

    __shared__ float red[256];
    red[j] = v; __syncthreads();
    for (int o = 128; o > 0; o >>= 1) { if (j < o) red[j] = fmaxf(red[j], red[j+o]); __syncthreads(); }
    float m = red[0]; __syncthreads();
    float e = expf(__fadd_rn(v, -m));
    red[j] = e; __syncthreads();
    for (int o = 128; o > 0; o >>= 1) { if (j < o) red[j] += red[j+o]; __syncthreads(); }
    p[j] = __fdiv_rn(e, red[0]);
}

// ---------------- CRF log-likelihood (per batch) ----------------
__global__ void crf_ll_k(const float* __restrict__ logits, const int* __restrict__ labels,
                         const int* __restrict__ lens, const float* __restrict__ trans,
                         float* __restrict__ ll)
{
    int b = blockIdx.x, j = threadIdx.x;
    __shared__ float tr[NLAB*NLAB];
    __shared__ float alpha[NLAB];
    for (int i = j; i < NLAB*NLAB; i += 32) tr[i] = trans[i];

    int len = lens[b];
    const float* lg = logits + (long)b*SEQ*NLAB;
    const int*   tg = labels + b*SEQ;

    float un = 0.f, bi = 0.f;
    for (int t = j; t < SEQ; t += 32) {
        if (t < len)                 un += lg[t*NLAB + tg[t]];
        if (t < SEQ-1 && t < len-1)  bi += trans[tg[t]*NLAB + tg[t+1]];
    }
    for (int o = 16; o > 0; o >>= 1) {
        un += __shfl_down_sync(0xffffffffu, un, o);
        bi += __shfl_down_sync(0xffffffffu, bi, o);
    }
    __syncwarp();
    if (j < NLAB) alpha[j] = lg[j];
    __syncwarp();

    int tend = len - 1;
    for (int t = 1; t <= tend; t++) {
        float na = 0.f;
        if (j < NLAB) {
            float m = -3.4e38f;
            for (int i = 0; i < NLAB; i++) m = fmaxf(m, alpha[i] + tr[i*NLAB + j]);
            float s = 0.f;
            for (int i = 0; i < NLAB; i++) s += expf(alpha[i] + tr[i*NLAB + j] - m);
            na = lg[t*NLAB + j] + m + logf(s);
        }
        __syncwarp();
        if (j < NLAB) alpha[j] = na;
        __syncwarp();
    }
    if (j == 0) {
        float m = -3.4e38f;
        for (int i = 0; i < NLAB; i++) m = fmaxf(m, alpha[i]);
        float s = 0.f;
        for (int i = 0; i < NLAB; i++) s += expf(alpha[i] - m);
        float lognorm = m + logf(s);
        ll[b] = (un + bi) - lognorm;
    }
}

// ---------------- Viterbi decode (per batch, shuffle-based, shared bp) ----------------
__global__ __launch_bounds__(32)
void viterbi_k(const float* __restrict__ logits, const float* __restrict__ trans,
               int* __restrict__ pred)
{
    const int b = blockIdx.x;
    const int j = threadIdx.x;
    const bool act = (j < NLAB);
    const int jj = act ? j : 0;

    __shared__ float tr[NLAB*NLAB];
    __shared__ int   bp[SEQ][NLAB];

    for (int i = j; i < NLAB*NLAB; i += 32) tr[i] = trans[i];
    __syncwarp();

    const float* lg = logits + (long)b*SEQ*NLAB;
    float vj = lg[jj];

    for (int t = 1; t < SEQ; t++) {
        float best = -3.4e38f;
        int   bi   = 0;
#pragma unroll
        for (int i = 0; i < NLAB; i++) {
            float vi = __shfl_sync(0xffffffffu, vj, i);
            float sc = __fadd_rn(vi, tr[i*NLAB + jj]);
            if (sc > best) { best = sc; bi = i; }   // first-max == jnp.argmax
        }
        vj = __fadd_rn(lg[t*NLAB + jj], best);
        if (act) bp[t][j] = bi;
    }

    float best = -3.4e38f;
    int   bt   = 0;
#pragma unroll
    for (int i = 0; i < NLAB; i++) {
        float vi = __shfl_sync(0xffffffffu, vj, i);
        if (vi > best) { best = vi; bt = i; }
    }
    __syncwarp();

    if (j == 0) {
        int cur = bt;
        pred[b*SEQ + SEQ-1] = cur;
        for (int t = SEQ-1; t >= 1; t--) {
            cur = bp[t][cur];
            pred[b*SEQ + t-1] = cur;
        }
    }
}

// ---------------- finalize: packed layout [loss | pred(B,T) | lens(B)] ----------------
__global__ void finalize_k(const float* __restrict__ ll, const int* __restrict__ pred,
                           const int* __restrict__ lens, float* __restrict__ out, int out_size)
{
    int idx = blockIdx.x*blockDim.x + threadIdx.x;
    if (idx == 0) {
        float s = 0.f;
        for (int b = 0; b < NBATCH; b++) s += ll[b];
        out[0] = -s / (float)NBATCH;
    }
    if (idx < NBATCH*SEQ && 1 + idx < out_size) out[1 + idx] = (float)pred[idx];
    if (idx < NBATCH && 1 + NBATCH*SEQ + idx < out_size) out[1 + NBATCH*SEQ + idx] = (float)lens[idx];
}

// ---------------- host glue ----------------
static void run_gemm(bool transb, const float* A, const float* Bm, const float* bias, float* C,
                     int M, int N, int K, int lda, int ldb, int ldc,
                     long sAo, long sAi, long sBo, long sBi, long sCo, long sCi,
                     int nInner, int batch)
{
    dim3 grid((N+127)/128, (M+127)/128, batch);
    if (transb) {
        if (bias) gemm_k<true ,true ><<<grid,256>>>(A,Bm,bias,C,M,N,K,lda,ldb,ldc,sAo,sAi,sBo,sBi,sCo,sCi,nInner);
        else      gemm_k<true ,false><<<grid,256>>>(A,Bm,bias,C,M,N,K,lda,ldb,ldc,sAo,sAi,sBo,sBi,sCo,sCi,nInner);
    } else {
        if (bias) gemm_k<false,true ><<<grid,256>>>(A,Bm,bias,C,M,N,K,lda,ldb,ldc,sAo,sAi,sBo,sBi,sCo,sCi,nInner);
        else      gemm_k<false,false><<<grid,256>>>(A,Bm,bias,C,M,N,K,lda,ldb,ldc,sAo,sAi,sBo,sBi,sCo,sCi,nInner);
    }
}

extern "C" void kernel_launch(void* const* d_in, const int* in_sizes, int n_in,
                              void* d_out, int out_size)
{
    const int* chars    = (const int*)d_in[0];
    const int* bounds   = (const int*)d_in[1];
    const int* flags    = (const int*)d_in[2];
    const int* radicals = (const int*)d_in[3];
    const int* pinyins  = (const int*)d_in[4];
    const int* labels   = (const int*)d_in[5];
    const float* e_char = (const float*)d_in[6];
    const float* e_bnd  = (const float*)d_in[7];
    const float* e_flag = (const float*)d_in[8];
    const float* e_rad  = (const float*)d_in[9];
    const float* e_pin  = (const float*)d_in[10];
    const float* Wx1f = (const float*)d_in[11], *Wh1f = (const float*)d_in[12], *b1f = (const float*)d_in[13];
    const float* Wx1b = (const float*)d_in[14], *Wh1b = (const float*)d_in[15], *b1b = (const float*)d_in[16];
    const float* Wx2f = (const float*)d_in[17], *Wh2f = (const float*)d_in[18], *b2f = (const float*)d_in[19];
    const float* Wx2b = (const float*)d_in[20], *Wh2b = (const float*)d_in[21], *b2b = (const float*)d_in[22];
    const float* Wq = (const float*)d_in[23], *Wk = (const float*)d_in[24], *Wv = (const float*)d_in[25];
    const float* Wo = (const float*)d_in[26], *bo = (const float*)d_in[27];
    const float* Wcrf = (const float*)d_in[28], *trans = (const float*)d_in[29];

    float *emb, *xwf, *xwb, *h1, *h2, *q, *k, *v, *s, *z, *ao, *logits, *ll;
    int *lens, *pred;
    cudaGetSymbolAddress((void**)&emb,    g_emb);
    cudaGetSymbolAddress((void**)&xwf,    g_xwf);
    cudaGetSymbolAddress((void**)&xwb,    g_xwb);
    cudaGetSymbolAddress((void**)&h1,     g_h1);
    cudaGetSymbolAddress((void**)&h2,     g_h2);
    cudaGetSymbolAddress((void**)&q,      g_q);
    cudaGetSymbolAddress((void**)&k,      g_k);
    cudaGetSymbolAddress((void**)&v,      g_v);
    cudaGetSymbolAddress((void**)&s,      g_s);
    cudaGetSymbolAddress((void**)&z,      g_z);
    cudaGetSymbolAddress((void**)&ao,     g_ao);
    cudaGetSymbolAddress((void**)&logits, g_logits);
    cudaGetSymbolAddress((void**)&ll,     g_ll);
    cudaGetSymbolAddress((void**)&lens,   g_lens);
    cudaGetSymbolAddress((void**)&pred,   g_pred);

    const int M = NBATCH*SEQ; // 16384

    embed_k<<<M, EDIM>>>(chars, bounds, flags, radicals, pinyins,
                         e_char, e_bnd, e_flag, e_rad, e_pin, emb);
    lens_k<<<NBATCH, SEQ>>>(chars, lens);

    run_gemm(false, emb, Wx1f, b1f, xwf, M, GATE, EDIM, EDIM, GATE, GATE, 0,0,0,0,0,0, 1, 1);
    run_gemm(false, emb, Wx1b, b1b, xwb, M, GATE, EDIM, EDIM, GATE, GATE, 0,0,0,0,0,0, 1, 1);
    lstm_k<<<dim3(NBATCH/2, 2), HID>>>(xwf, xwb, Wh1f, Wh1b, h1);

    run_gemm(false, h1, Wx2f, b2f, xwf, M, GATE, DD2, DD2, GATE, GATE, 0,0,0,0,0,0, 1, 1);
    run_gemm(false, h1, Wx2b, b2b, xwb, M, GATE, DD2, DD2, GATE, GATE, 0,0,0,0,0,0, 1, 1);
    lstm_k<<<dim3(NBATCH/2, 2), HID>>>(xwf, xwb, Wh2f, Wh2b, h2);

    run_gemm(false, h2, Wq, nullptr, q, M, ADIM, DD2, DD2, ADIM, ADIM, 0,0,0,0,0,0, 1, 1);
    run_gemm(false, h2, Wk, nullptr, k, M, ADIM, DD2, DD2, ADIM, ADIM, 0,0,0,0,0,0, 1, 1);
    run_gemm(false, h2, Wv, nullptr, v, M, ADIM, DD2, DD2, ADIM, ADIM, 0,0,0,0,0,0, 1, 1);

    // scores S[b,h] = Q[b,:,h*128:...] @ K^T  (batched, TRANSB)
    run_gemm(true, q, k, nullptr, s, SEQ, SEQ, HDIM, ADIM, ADIM, SEQ,
             (long)SEQ*ADIM, HDIM, (long)SEQ*ADIM, HDIM,
             (long)NHEAD*SEQ*SEQ, (long)SEQ*SEQ, NHEAD, NBATCH*NHEAD);
    softmax_k<<<NBATCH*NHEAD*SEQ, SEQ>>>(s, lens);

    // Z[b,h] = P @ V[b,:,h*128:...]  — stored contiguously as (b, h, q, d):
    // reading g_z as (B, T, 512) row-major reproduces the reference's
    // Z.reshape(B, T, H*d) (reinterpret of (B,H,T,d) without transpose back).
    run_gemm(false, s, v, nullptr, z, SEQ, HDIM, SEQ, SEQ, ADIM, HDIM,
             (long)NHEAD*SEQ*SEQ, (long)SEQ*SEQ, (long)SEQ*ADIM, HDIM,
             (long)SEQ*ADIM, (long)SEQ*HDIM, NHEAD, NBATCH*NHEAD);

    run_gemm(false, z, Wo, bo, ao, M, ADIM, ADIM, ADIM, ADIM, ADIM, 0,0,0,0,0,0, 1, 1);
    run_gemm(false, ao, Wcrf, nullptr, logits, M, NLAB, ADIM, ADIM, NLAB, NLAB, 0,0,0,0,0,0, 1, 1);

    crf_ll_k<<<NBATCH, 32>>>(logits, labels, lens, trans, ll);
    viterbi_k<<<NBATCH, 32>>>(logits, trans, pred);
    finalize_k<<<(NBATCH*SEQ + 255)/256, 256>>>(ll, pred, lens, (float*)d_out, out_size);
}

// round 13
// speedup vs baseline: 1.0072x; 1.0022x over previous
#include <cuda_runtime.h>
#include <math.h>

// ---------------- problem dims ----------------
#define NBATCH 64
#define SEQ    256
#define EDIM   352
#define HID    384
#define GATE   1536   // 4*HID
#define DD2    768    // 2*HID
#define ADIM   512
#define NHEAD  4
#define HDIM   128
#define NLAB   31

// ---------------- scratch (device globals; no cudaMalloc allowed) ----------------
__device__ float g_emb   [NBATCH*SEQ*EDIM];
__device__ float g_xwf   [NBATCH*SEQ*GATE];
__device__ float g_xwb   [NBATCH*SEQ*GATE];
__device__ float g_h1    [NBATCH*SEQ*DD2];
__device__ float g_h2    [NBATCH*SEQ*DD2];
__device__ float g_q     [NBATCH*SEQ*ADIM];
__device__ float g_k     [NBATCH*SEQ*ADIM];
__device__ float g_v     [NBATCH*SEQ*ADIM];
__device__ float g_s     [NBATCH*NHEAD*SEQ*SEQ];
__device__ float g_z     [NBATCH*SEQ*ADIM];
__device__ float g_ao    [NBATCH*SEQ*ADIM];
__device__ float g_logits[NBATCH*SEQ*NLAB];
__device__ float g_ll    [NBATCH];
__device__ int   g_lens  [NBATCH];
__device__ int   g_pred  [NBATCH*SEQ];

// XLA LogisticExpander form: logistic(x) = 0.5 + 0.5 * tanh(0.5 * x)
__device__ __forceinline__ float xla_sigmoid(float x) {
    return __fadd_rn(0.5f, __fmul_rn(0.5f, tanhf(__fmul_rn(0.5f, x))));
}

// ---------------- embedding concat ----------------
__global__ void embed_k(const int* __restrict__ chars, const int* __restrict__ bounds,
                        const int* __restrict__ flags, const int* __restrict__ radicals,
                        const int* __restrict__ pinyins,
                        const float* __restrict__ ec, const float* __restrict__ eb,
                        const float* __restrict__ ef, const float* __restrict__ er,
                        const float* __restrict__ ep, float* __restrict__ emb)
{
    int bt = blockIdx.x;
    int f  = threadIdx.x; // 0..351
    float v;
    if      (f < 128) v = ec[(long)chars[bt]   *128 + f];
    else if (f < 160) v = eb[(long)bounds[bt]  *32  + (f-128)];
    else if (f < 224) v = ef[(long)flags[bt]   *64  + (f-160)];
    else if (f < 288) v = er[(long)radicals[bt]*64  + (f-224)];
    else              v = ep[(long)pinyins[bt] *64  + (f-288)];
    emb[(long)bt*EDIM + f] = v;
}

__global__ void lens_k(const int* __restrict__ chars, int* __restrict__ lens)
{
    __shared__ int cnt;
    if (threadIdx.x == 0) cnt = 0;
    __syncthreads();
    int c = chars[blockIdx.x*SEQ + threadIdx.x];
    int sg = (c > 0) - (c < 0);
    atomicAdd(&cnt, sg);
    __syncthreads();
    if (threadIdx.x == 0) lens[blockIdx.x] = cnt;
}

// ---------------- generic tiled GEMM (exact fp32, fma accumulate) ----------------
template<bool TRANSB, bool BIAS>
__global__ __launch_bounds__(256)
void gemm_k(const float* __restrict__ A0, const float* __restrict__ B0,
            const float* __restrict__ bias, float* __restrict__ C0,
            int M, int N, int K, int lda, int ldb, int ldc,
            long sAo, long sAi, long sBo, long sBi, long sCo, long sCi, int nInner)
{
    int z  = blockIdx.z;
    int zo = z / nInner, zi = z - zo*nInner;
    const float* A  = A0 + zo*sAo + zi*sAi;
    const float* Bp = B0 + zo*sBo + zi*sBi;
    float*       C  = C0 + zo*sCo + zi*sCi;

    int m0 = blockIdx.y*128, n0 = blockIdx.x*128;
    __shared__ float As[8][128];
    __shared__ float Bs[8][128];

    int tid = threadIdx.x;
    int ty = tid >> 4, tx = tid & 15;

    float acc[8][8];
#pragma unroll
    for (int i = 0; i < 8; i++)
#pragma unroll
        for (int j = 0; j < 8; j++) acc[i][j] = 0.f;

    const int ar = tid >> 1, ak = (tid & 1) << 2;
    const bool bvec_ok = ((ldb & 3) == 0);

    for (int k0 = 0; k0 < K; k0 += 8) {
        float4 av = make_float4(0.f,0.f,0.f,0.f);
        if (m0 + ar < M)
            av = *(const float4*)(A + (long)(m0+ar)*lda + k0 + ak);
        As[ak+0][ar]=av.x; As[ak+1][ar]=av.y; As[ak+2][ar]=av.z; As[ak+3][ar]=av.w;

        if (TRANSB) {
            int br = tid >> 1, bk = (tid & 1) << 2;
            float4 bv = make_float4(0.f,0.f,0.f,0.f);
            if (n0 + br < N)
                bv = *(const float4*)(Bp + (long)(n0+br)*ldb + k0 + bk);
            Bs[bk+0][br]=bv.x; Bs[bk+1][br]=bv.y; Bs[bk+2][br]=bv.z; Bs[bk+3][br]=bv.w;
        } else {
            int bk = tid >> 5, bn = (tid & 31) << 2;
            const float* pb = Bp + (long)(k0+bk)*ldb + n0 + bn;
            if (bvec_ok && (n0 + bn + 4 <= N)) {
                float4 bv = *(const float4*)pb;
                Bs[bk][bn+0]=bv.x; Bs[bk][bn+1]=bv.y; Bs[bk][bn+2]=bv.z; Bs[bk][bn+3]=bv.w;
            } else {
#pragma unroll
                for (int i = 0; i < 4; i++)
                    Bs[bk][bn+i] = (n0 + bn + i < N) ? pb[i] : 0.f;
            }
        }
        __syncthreads();

#pragma unroll
        for (int kk = 0; kk < 8; kk++) {
            float a[8], b[8];
            *(float4*)(a)   = *(const float4*)&As[kk][ty<<3];
            *(float4*)(a+4) = *(const float4*)&As[kk][(ty<<3)+4];
            *(float4*)(b)   = *(const float4*)&Bs[kk][tx<<3];
            *(float4*)(b+4) = *(const float4*)&Bs[kk][(tx<<3)+4];
#pragma unroll
            for (int i = 0; i < 8; i++)
#pragma unroll
                for (int j = 0; j < 8; j++)
                    acc[i][j] = fmaf(a[i], b[j], acc[i][j]);
        }
        __syncthreads();
    }

#pragma unroll
    for (int i = 0; i < 8; i++) {
        int row = m0 + (ty<<3) + i;
        if (row >= M) continue;
#pragma unroll
        for (int j = 0; j < 8; j++) {
            int col = n0 + (tx<<3) + j;
            if (col < N) {
                float v = acc[i][j];
                if (BIAS) v = __fadd_rn(v, bias[col]);
                C[(long)row*ldc + col] = v;
            }
        }
    }
}

// ---------------- LSTM recurrence (exact fp32) ----------------
__global__ __launch_bounds__(384)
void lstm_k(const float* __restrict__ xwF, const float* __restrict__ xwB,
            const float* __restrict__ WhF, const float* __restrict__ WhB,
            float* __restrict__ out)
{
    const int dir = blockIdx.y;
    const int b0  = blockIdx.x * 2;
    const float* xw = dir ? xwB : xwF;
    const float* Wh = dir ? WhB : WhF;

    __shared__ float2 hs[HID];
    __shared__ float  zs[2][GATE];

    const int u = threadIdx.x;
    float c0 = 0.f, c1 = 0.f;
    hs[u] = make_float2(0.f, 0.f);
    __syncthreads();

    const float* w = Wh + 4*u;

    for (int t = 0; t < SEQ; t++) {
        const int tin = dir ? (SEQ-1-t) : t;
        float4 a0 = *(const float4*)&xw[((long)(b0+0)*SEQ + tin)*GATE + 4*u];
        float4 a1 = *(const float4*)&xw[((long)(b0+1)*SEQ + tin)*GATE + 4*u];

#pragma unroll 8
        for (int k = 0; k < HID; k++) {
            float4 wv = *(const float4*)&w[(long)k*GATE];
            float2 h = hs[k];
            a0.x = fmaf(h.x, wv.x, a0.x); a0.y = fmaf(h.x, wv.y, a0.y);
            a0.z = fmaf(h.x, wv.z, a0.z); a0.w = fmaf(h.x, wv.w, a0.w);
            a1.x = fmaf(h.y, wv.x, a1.x); a1.y = fmaf(h.y, wv.y, a1.y);
            a1.z = fmaf(h.y, wv.z, a1.z); a1.w = fmaf(h.y, wv.w, a1.w);
        }
        *(float4*)&zs[0][4*u] = a0;
        *(float4*)&zs[1][4*u] = a1;
        __syncthreads();

        float zi0 = zs[0][u], zf0 = zs[0][u+HID], zg0 = zs[0][u+2*HID], zo0 = zs[0][u+3*HID];
        float zi1 = zs[1][u], zf1 = zs[1][u+HID], zg1 = zs[1][u+2*HID], zo1 = zs[1][u+3*HID];
        float i0 = xla_sigmoid(zi0), f0 = xla_sigmoid(zf0), o0 = xla_sigmoid(zo0);
        float i1 = xla_sigmoid(zi1), f1 = xla_sigmoid(zf1), o1 = xla_sigmoid(zo1);
        c0 = __fadd_rn(__fmul_rn(f0, c0), __fmul_rn(i0, tanhf(zg0)));
        c1 = __fadd_rn(__fmul_rn(f1, c1), __fmul_rn(i1, tanhf(zg1)));
        float h0 = __fmul_rn(o0, tanhf(c0));
        float h1 = __fmul_rn(o1, tanhf(c1));
        hs[u] = make_float2(h0, h1);
        out[((long)(b0+0)*SEQ + t)*DD2 + dir*HID + u] = h0;
        out[((long)(b0+1)*SEQ + t)*DD2 + dir*HID + u] = h1;
        __syncthreads();
    }
}

// ---------------- masked, scaled softmax over key dim ----------------
__global__ void softmax_k(float* __restrict__ s, const int* __restrict__ lens)
{
    long row = blockIdx.x;
    int  b   = blockIdx.x >> 10;
    float* p = s + row*SEQ;
    int len  = lens[b];
    int j    = threadIdx.x;

    const float rs = sqrtf(512.0f);
    float raw = (j < len) ? p[j] : -4294967296.0f;
    float v = __fdiv_rn(raw, rs);

    __shared__ float red[256];
    red[j] = v; __syncthreads();
    for (int o = 128; o > 0; o >>= 1) { if (j < o) red[j] = fmaxf(red[j], red[j+o]); __syncthreads(); }
    float m = red[0]; __syncthreads();
    float e = expf(__fadd_rn(v, -m));
    red[j] = e; __syncthreads();
    for (int o = 128; o > 0; o >>= 1) { if (j < o) red[j] += red[j+o]; __syncthreads(); }
    p[j] = __fdiv_rn(e, red[0]);
}

// ---------------- CRF log-likelihood (per batch) ----------------
__global__ void crf_ll_k(const float* __restrict__ logits, const int* __restrict__ labels,
                         const int* __restrict__ lens, const float* __restrict__ trans,
                         float* __restrict__ ll)
{
    int b = blockIdx.x, j = threadIdx.x;
    __shared__ float tr[NLAB*NLAB];
    __shared__ float alpha[NLAB];
    for (int i = j; i < NLAB*NLAB; i += 32) tr[i] = trans[i];

    int len = lens[b];
    const float* lg = logits + (long)b*SEQ*NLAB;
    const int*   tg = labels + b*SEQ;

    float un = 0.f, bi = 0.f;
    for (int t = j; t < SEQ; t += 32) {
        if (t < len)                 un += lg[t*NLAB + tg[t]];
        if (t < SEQ-1 && t < len-1)  bi += trans[tg[t]*NLAB + tg[t+1]];
    }
    for (int o = 16; o > 0; o >>= 1) {
        un += __shfl_down_sync(0xffffffffu, un, o);
        bi += __shfl_down_sync(0xffffffffu, bi, o);
    }
    __syncwarp();
    if (j < NLAB) alpha[j] = lg[j];
    __syncwarp();

    int tend = len - 1;
    for (int t = 1; t <= tend; t++) {
        float na = 0.f;
        if (j < NLAB) {
            float m = -3.4e38f;
            for (int i = 0; i < NLAB; i++) m = fmaxf(m, alpha[i] + tr[i*NLAB + j]);
            float s = 0.f;
            for (int i = 0; i < NLAB; i++) s += expf(alpha[i] + tr[i*NLAB + j] - m);
            na = lg[t*NLAB + j] + m + logf(s);
        }
        __syncwarp();
        if (j < NLAB) alpha[j] = na;
        __syncwarp();
    }
    if (j == 0) {
        float m = -3.4e38f;
        for (int i = 0; i < NLAB; i++) m = fmaxf(m, alpha[i]);
        float s = 0.f;
        for (int i = 0; i < NLAB; i++) s += expf(alpha[i] - m);
        float lognorm = m + logf(s);
        ll[b] = (un + bi) - lognorm;
    }
}

// ---------------- Viterbi decode (per batch, shuffle-based, shared bp) ----------------
__global__ __launch_bounds__(32)
void viterbi_k(const float* __restrict__ logits, const float* __restrict__ trans,
               int* __restrict__ pred)
{
    const int b = blockIdx.x;
    const int j = threadIdx.x;
    const bool act = (j < NLAB);
    const int jj = act ? j : 0;

    __shared__ float tr[NLAB*NLAB];
    __shared__ int   bp[SEQ][NLAB];

    for (int i = j; i < NLAB*NLAB; i += 32) tr[i] = trans[i];
    __syncwarp();

    const float* lg = logits + (long)b*SEQ*NLAB;
    float vj = lg[jj];

    for (int t = 1; t < SEQ; t++) {
        float best = -3.4e38f;
        int   bi   = 0;
#pragma unroll
        for (int i = 0; i < NLAB; i++) {
            float vi = __shfl_sync(0xffffffffu, vj, i);
            float sc = __fadd_rn(vi, tr[i*NLAB + jj]);
            if (sc > best) { best = sc; bi = i; }   // first-max == jnp.argmax
        }
        vj = __fadd_rn(lg[t*NLAB + jj], best);
        if (act) bp[t][j] = bi;
    }

    float best = -3.4e38f;
    int   bt   = 0;
#pragma unroll
    for (int i = 0; i < NLAB; i++) {
        float vi = __shfl_sync(0xffffffffu, vj, i);
        if (vi > best) { best = vi; bt = i; }
    }
    __syncwarp();

    if (j == 0) {
        int cur = bt;
        pred[b*SEQ + SEQ-1] = cur;
        for (int t = SEQ-1; t >= 1; t--) {
            cur = bp[t][cur];
            pred[b*SEQ + t-1] = cur;
        }
    }
}

// ---------------- finalize: packed layout [loss | pred(B,T) | lens(B)] ----------------
__global__ void finalize_k(const float* __restrict__ ll, const int* __restrict__ pred,
                           const int* __restrict__ lens, float* __restrict__ out, int out_size)
{
    int idx = blockIdx.x*blockDim.x + threadIdx.x;
    if (idx == 0) {
        float s = 0.f;
        for (int b = 0; b < NBATCH; b++) s += ll[b];
        out[0] = -s / (float)NBATCH;
    }
    if (idx < NBATCH*SEQ && 1 + idx < out_size) out[1 + idx] = (float)pred[idx];
    if (idx < NBATCH && 1 + NBATCH*SEQ + idx < out_size) out[1 + NBATCH*SEQ + idx] = (float)lens[idx];
}

// ---------------- host glue ----------------
static void run_gemm(bool transb, const float* A, const float* Bm, const float* bias, float* C,
                     int M, int N, int K, int lda, int ldb, int ldc,
                     long sAo, long sAi, long sBo, long sBi, long sCo, long sCi,
                     int nInner, int batch)
{
    dim3 grid((N+127)/128, (M+127)/128, batch);
    if (transb) {
        if (bias) gemm_k<true ,true ><<<grid,256>>>(A,Bm,bias,C,M,N,K,lda,ldb,ldc,sAo,sAi,sBo,sBi,sCo,sCi,nInner);
        else      gemm_k<true ,false><<<grid,256>>>(A,Bm,bias,C,M,N,K,lda,ldb,ldc,sAo,sAi,sBo,sBi,sCo,sCi,nInner);
    } else {
        if (bias) gemm_k<false,true ><<<grid,256>>>(A,Bm,bias,C,M,N,K,lda,ldb,ldc,sAo,sAi,sBo,sBi,sCo,sCi,nInner);
        else      gemm_k<false,false><<<grid,256>>>(A,Bm,bias,C,M,N,K,lda,ldb,ldc,sAo,sAi,sBo,sBi,sCo,sCi,nInner);
    }
}

extern "C" void kernel_launch(void* const* d_in, const int* in_sizes, int n_in,
                              void* d_out, int out_size)
{
    const int* chars    = (const int*)d_in[0];
    const int* bounds   = (const int*)d_in[1];
    const int* flags    = (const int*)d_in[2];
    const int* radicals = (const int*)d_in[3];
    const int* pinyins  = (const int*)d_in[4];
    const int* labels   = (const int*)d_in[5];
    const float* e_char = (const float*)d_in[6];
    const float* e_bnd  = (const float*)d_in[7];
    const float* e_flag = (const float*)d_in[8];
    const float* e_rad  = (const float*)d_in[9];
    const float* e_pin  = (const float*)d_in[10];
    const float* Wx1f = (const float*)d_in[11], *Wh1f = (const float*)d_in[12], *b1f = (const float*)d_in[13];
    const float* Wx1b = (const float*)d_in[14], *Wh1b = (const float*)d_in[15], *b1b = (const float*)d_in[16];
    const float* Wx2f = (const float*)d_in[17], *Wh2f = (const float*)d_in[18], *b2f = (const float*)d_in[19];
    const float* Wx2b = (const float*)d_in[20], *Wh2b = (const float*)d_in[21], *b2b = (const float*)d_in[22];
    const float* Wq = (const float*)d_in[23], *Wk = (const float*)d_in[24], *Wv = (const float*)d_in[25];
    const float* Wo = (const float*)d_in[26], *bo = (const float*)d_in[27];
    const float* Wcrf = (const float*)d_in[28], *trans = (const float*)d_in[29];

    float *emb, *xwf, *xwb, *h1, *h2, *q, *k, *v, *s, *z, *ao, *logits, *ll;
    int *lens, *pred;
    cudaGetSymbolAddress((void**)&emb,    g_emb);
    cudaGetSymbolAddress((void**)&xwf,    g_xwf);
    cudaGetSymbolAddress((void**)&xwb,    g_xwb);
    cudaGetSymbolAddress((void**)&h1,     g_h1);
    cudaGetSymbolAddress((void**)&h2,     g_h2);
    cudaGetSymbolAddress((void**)&q,      g_q);
    cudaGetSymbolAddress((void**)&k,      g_k);
    cudaGetSymbolAddress((void**)&v,      g_v);
    cudaGetSymbolAddress((void**)&s,      g_s);
    cudaGetSymbolAddress((void**)&z,      g_z);
    cudaGetSymbolAddress((void**)&ao,     g_ao);
    cudaGetSymbolAddress((void**)&logits, g_logits);
    cudaGetSymbolAddress((void**)&ll,     g_ll);
    cudaGetSymbolAddress((void**)&lens,   g_lens);
    cudaGetSymbolAddress((void**)&pred,   g_pred);

    const int M = NBATCH*SEQ; // 16384

    embed_k<<<M, EDIM>>>(chars, bounds, flags, radicals, pinyins,
                         e_char, e_bnd, e_flag, e_rad, e_pin, emb);
    lens_k<<<NBATCH, SEQ>>>(chars, lens);

    run_gemm(false, emb, Wx1f, b1f, xwf, M, GATE, EDIM, EDIM, GATE, GATE, 0,0,0,0,0,0, 1, 1);
    run_gemm(false, emb, Wx1b, b1b, xwb, M, GATE, EDIM, EDIM, GATE, GATE, 0,0,0,0,0,0, 1, 1);
    lstm_k<<<dim3(NBATCH/2, 2), HID>>>(xwf, xwb, Wh1f, Wh1b, h1);

    run_gemm(false, h1, Wx2f, b2f, xwf, M, GATE, DD2, DD2, GATE, GATE, 0,0,0,0,0,0, 1, 1);
    run_gemm(false, h1, Wx2b, b2b, xwb, M, GATE, DD2, DD2, GATE, GATE, 0,0,0,0,0,0, 1, 1);
    lstm_k<<<dim3(NBATCH/2, 2), HID>>>(xwf, xwb, Wh2f, Wh2b, h2);

    run_gemm(false, h2, Wq, nullptr, q, M, ADIM, DD2, DD2, ADIM, ADIM, 0,0,0,0,0,0, 1, 1);
    run_gemm(false, h2, Wk, nullptr, k, M, ADIM, DD2, DD2, ADIM, ADIM, 0,0,0,0,0,0, 1, 1);
    run_gemm(false, h2, Wv, nullptr, v, M, ADIM, DD2, DD2, ADIM, ADIM, 0,0,0,0,0,0, 1, 1);

    // scores S[b,h] = Q[b,:,h*128:...] @ K^T  (batched, TRANSB)
    run_gemm(true, q, k, nullptr, s, SEQ, SEQ, HDIM, ADIM, ADIM, SEQ,
             (long)SEQ*ADIM, HDIM, (long)SEQ*ADIM, HDIM,
             (long)NHEAD*SEQ*SEQ, (long)SEQ*SEQ, NHEAD, NBATCH*NHEAD);
    softmax_k<<<NBATCH*NHEAD*SEQ, SEQ>>>(s, lens);

    // Z[b,h] = P @ V[b,:,h*128:...]  — stored contiguously as (b, h, q, d):
    // reading g_z as (B, T, 512) row-major reproduces the reference's
    // Z.reshape(B, T, H*d) (reinterpret of (B,H,T,d) without transpose back).
    run_gemm(false, s, v, nullptr, z, SEQ, HDIM, SEQ, SEQ, ADIM, HDIM,
             (long)NHEAD*SEQ*SEQ, (long)SEQ*SEQ, (long)SEQ*ADIM, HDIM,
             (long)SEQ*ADIM, (long)SEQ*HDIM, NHEAD, NBATCH*NHEAD);

    run_gemm(false, z, Wo, bo, ao, M, ADIM, ADIM, ADIM, ADIM, ADIM, 0,0,0,0,0,0, 1, 1);
    run_gemm(false, ao, Wcrf, nullptr, logits, M, NLAB, ADIM, ADIM, NLAB, NLAB, 0,0,0,0,0,0, 1, 1);

    crf_ll_k<<<NBATCH, 32>>>(logits, labels, lens, trans, ll);
    viterbi_k<<<NBATCH, 32>>>(logits, trans, pred);
    finalize_k<<<(NBATCH*SEQ + 255)/256, 256>>>(ll, pred, lens, (float*)d_out, out_size);
}